// round 8
// baseline (speedup 1.0000x reference)
#include <cuda_runtime.h>
#include <cuda_fp16.h>
#include <cstdint>
#include <cstddef>

#define D_MODEL 2048
#define LSEQ    4096
#define BDIM    2
#define NTOK    (BDIM * LSEQ)      // 8192
#define NHEAD   16
#define HIDDEN  5632
#define NCHUNK  32
#define CLEN    (LSEQ / NCHUNK)    // 128

// ---------------- scratch (device globals; no allocation allowed) ----------------
__device__ __half g_xn [(size_t)NTOK * D_MODEL];
__device__ float  g_qk [(size_t)NTOK * 2048];             // q | k*scale
__device__ float  g_eg [(size_t)NTOK * 1024];
__device__ float  g_t16[(size_t)NTOK * 16];
__device__ float  g_v  [(size_t)NTOK * D_MODEL];
__device__ float  g_gt [(size_t)NTOK * D_MODEL];
__device__ float  g_o  [(size_t)NTOK * D_MODEL];
__device__ __half g_oh [(size_t)NTOK * D_MODEL];
__device__ float  g_x2 [(size_t)NTOK * D_MODEL];
__device__ __half g_h1h[(size_t)NTOK * HIDDEN];
__device__ __half g_wt [51380224];
__device__ float  g_Tc [(size_t)NCHUNK * 64 * 64 * 64];   // per-chunk local state
__device__ float  g_Pc [(size_t)NCHUNK * 64 * 64];        // per-chunk gate product
__device__ float  g_Sst[(size_t)NCHUNK * 64 * 64 * 64];   // state entering chunk

__device__ __forceinline__ float siluf(float x) { return x / (1.f + __expf(-x)); }
__device__ __forceinline__ void cpa16(void* s, const void* g) {
    uint32_t a = (uint32_t)__cvta_generic_to_shared(s);
    asm volatile("cp.async.cg.shared.global [%0], [%1], 16;" :: "r"(a), "l"(g));
}

// ================= fp16 tensor-core GEMM =================
// C[M,N] = epi(A[M,K] @ Wt[N,K]^T). CTA 128x128, 128 threads, 4 warps (2m x 2n),
// warp tile 64x64. BK=64, 3 stages, 2 CTAs/SM.
enum { EPI_QKVG = 0, EPI_RES = 3, EPI_SWIGLU = 5 };

#define BK    64
#define LDH   72                           // halves/row: 144B (16B-aligned, ldsm conflict-free)
#define AH    (128 * LDH)                  // 9216 halves
#define STGH  (2 * AH)                     // A + B
#define NST   3
#define GSMEM (NST * STGH * 2)             // 110592 B

#define LDSM4(r, a)                                                            \
    asm volatile("ldmatrix.sync.aligned.m8n8.x4.shared.b16 {%0,%1,%2,%3}, [%4];" \
        : "=r"((r)[0]), "=r"((r)[1]), "=r"((r)[2]), "=r"((r)[3]) : "r"(a))

__device__ __forceinline__ void mma_h(float* c, const uint32_t* a, const uint32_t* b) {
    asm volatile(
        "mma.sync.aligned.m16n8k16.row.col.f32.f16.f16.f32 "
        "{%0,%1,%2,%3}, {%4,%5,%6,%7}, {%8,%9}, {%0,%1,%2,%3};"
        : "+f"(c[0]), "+f"(c[1]), "+f"(c[2]), "+f"(c[3])
        : "r"(a[0]), "r"(a[1]), "r"(a[2]), "r"(a[3]), "r"(b[0]), "r"(b[1]));
}

template <int EPI>
__global__ __launch_bounds__(128, 2) void gemm_h(
    const __half* __restrict__ A, const __half* __restrict__ Wt, void* __restrict__ Cv,
    int M, int N, int K,
    const float* __restrict__ bias, const float* __restrict__ res,
    const float* __restrict__ aux)
{
    extern __shared__ __align__(16) __half hsm[];
    const int tid = threadIdx.x;
    const int wid = tid >> 5, lane = tid & 31;
    const int g = lane >> 2, tig = lane & 3;
    const int wm = (wid >> 1) * 64;
    const int wn = (wid & 1) * 64;
    const int m0 = blockIdx.y * 128;
    const int n0 = blockIdx.x * 128;
    const int nK = K >> 6;

    auto load_stage = [&](int slot, int kc) {
        __half* As = hsm + slot * STGH;
        __half* Bs = As + AH;
        const int k0 = kc * BK;
        const __half* Ag = A  + (size_t)m0 * K + k0;
        const __half* Bg = Wt + (size_t)n0 * K + k0;
        #pragma unroll
        for (int j = 0; j < 8; j++) {          // 1024 chunks each for A and B
            const int i = tid + j * 128;
            const int row = i >> 3, c = i & 7;
            cpa16(As + row * LDH + c * 8, Ag + (size_t)row * K + c * 8);
            cpa16(Bs + row * LDH + c * 8, Bg + (size_t)row * K + c * 8);
        }
        asm volatile("cp.async.commit_group;");
    };

    float acc[4][8][4];
    #pragma unroll
    for (int mt = 0; mt < 4; mt++)
        #pragma unroll
        for (int nt = 0; nt < 8; nt++)
            #pragma unroll
            for (int r = 0; r < 4; r++) acc[mt][nt][r] = 0.f;

    load_stage(0, 0);
    load_stage(1, 1);

    const uint32_t sbase = (uint32_t)__cvta_generic_to_shared(hsm);
    const int lrA = lane & 15;
    const int lkA = (lane >> 4) << 3;
    const int rB  = (lane & 7) + ((lane & 16) ? 8 : 0);
    const int lkB = (lane & 8) ? 8 : 0;

    for (int ks = 0; ks < nK; ks++) {
        const int slot = ks % 3;
        if (ks + 1 < nK) asm volatile("cp.async.wait_group 1;");
        else             asm volatile("cp.async.wait_group 0;");
        __syncthreads();
        if (ks + 2 < nK) load_stage((ks + 2) % 3, ks + 2);

        const uint32_t aB = sbase + (uint32_t)(slot * STGH) * 2;
        const uint32_t bB = aB + AH * 2;
        const uint32_t aAddr = aB + (uint32_t)((wm + lrA) * LDH + lkA) * 2;
        const uint32_t bAddr = bB + (uint32_t)((wn + rB) * LDH + lkB) * 2;

        #pragma unroll
        for (int kstep = 0; kstep < 4; kstep++) {
            uint32_t a[4][4], b[4][4];
            #pragma unroll
            for (int mt = 0; mt < 4; mt++)
                LDSM4(a[mt], aAddr + (uint32_t)(mt * 16 * LDH) * 2 + kstep * 32);
            #pragma unroll
            for (int np = 0; np < 4; np++)
                LDSM4(b[np], bAddr + (uint32_t)(np * 16 * LDH) * 2 + kstep * 32);
            #pragma unroll
            for (int mt = 0; mt < 4; mt++)
                #pragma unroll
                for (int nt = 0; nt < 8; nt++)
                    mma_h(acc[mt][nt], a[mt], &b[nt >> 1][(nt & 1) * 2]);
        }
    }

    // ---- epilogue ----
    #pragma unroll
    for (int mt = 0; mt < 4; mt++) {
        #pragma unroll
        for (int hf = 0; hf < 2; hf++) {
            const size_t row = (size_t)m0 + wm + mt * 16 + g + hf * 8;
            #pragma unroll
            for (int nt = 0; nt < 8; nt++) {
                const int col = n0 + wn + nt * 8 + tig * 2;
                float v0 = acc[mt][nt][hf * 2 + 0];
                float v1 = acc[mt][nt][hf * 2 + 1];
                if (EPI == EPI_QKVG) {
                    // regions: [0,2048)=qk  [2048,4096)=v  [4096,6144)=g(+bias)
                    float* dst;
                    int cl = col;
                    if (n0 < 2048)      { dst = (float*)Cv; }
                    else if (n0 < 4096) { dst = (float*)res; cl -= 2048; }
                    else {
                        dst = (float*)aux; cl -= 4096;
                        v0 += bias[cl]; v1 += bias[cl + 1];
                    }
                    *(float2*)(dst + row * 2048 + cl) = make_float2(v0, v1);
                } else if (EPI == EPI_RES) {
                    const size_t base = row * (size_t)N + col;
                    const float2 rv = *(const float2*)(res + base);
                    *(float2*)((float*)Cv + base) = make_float2(v0 + rv.x, v1 + rv.y);
                } else { // EPI_SWIGLU
                    ((__half*)Cv)[row * (size_t)(N >> 1) + (col >> 1)] =
                        __float2half_rn(siluf(v0) * v1);
                }
            }
        }
    }
}

// ------- 32x32 tiled transpose + fp16 convert; out row = c*rowMul + rowOff -------
__global__ __launch_bounds__(256) void transpose_h(const float* __restrict__ in,
                                                   __half* __restrict__ out,
                                                   int R, int Ccols, float scale,
                                                   int rowMul, int rowOff)
{
    __shared__ float tile[32][33];
    const int c0 = blockIdx.x * 32, r0 = blockIdx.y * 32;
    const int x = threadIdx.x & 31, y = threadIdx.x >> 5;
    #pragma unroll
    for (int i = 0; i < 32; i += 8)
        tile[y + i][x] = in[(size_t)(r0 + y + i) * Ccols + c0 + x] * scale;
    __syncthreads();
    #pragma unroll
    for (int i = 0; i < 32; i += 8)
        out[((size_t)(c0 + y + i) * rowMul + rowOff) * R + r0 + x] =
            __float2half_rn(tile[x][y + i]);
}

// ---------------- RMSNorm: fp32 in -> half out ----------------
__global__ __launch_bounds__(256) void rmsnorm_k(const float* __restrict__ x,
                                                 const float* __restrict__ w,
                                                 __half* __restrict__ y)
{
    const int row = blockIdx.x;
    const int tid = threadIdx.x;
    const float4* xr = (const float4*)(x + (size_t)row * D_MODEL);
    float4 v0 = xr[tid];
    float4 v1 = xr[tid + 256];
    float ss = v0.x*v0.x + v0.y*v0.y + v0.z*v0.z + v0.w*v0.w
             + v1.x*v1.x + v1.y*v1.y + v1.z*v1.z + v1.w*v1.w;
    #pragma unroll
    for (int off = 16; off; off >>= 1) ss += __shfl_xor_sync(0xffffffffu, ss, off);
    __shared__ float red[8];
    if ((tid & 31) == 0) red[tid >> 5] = ss;
    __syncthreads();
    if (tid < 32) {
        float t = (tid < 8) ? red[tid] : 0.f;
        #pragma unroll
        for (int off = 4; off; off >>= 1) t += __shfl_xor_sync(0xffffffffu, t, off);
        if (tid == 0) red[0] = t;
    }
    __syncthreads();
    const float scale = rsqrtf(red[0] * (1.f / (float)D_MODEL) + 1e-5f);
    const float4* wr = (const float4*)w;
    float4 w0 = wr[tid], w1 = wr[tid + 256];
    __half2* y2 = (__half2*)(y + (size_t)row * D_MODEL);
    y2[tid * 2]       = __floats2half2_rn(v0.x * scale * w0.x, v0.y * scale * w0.y);
    y2[tid * 2 + 1]   = __floats2half2_rn(v0.z * scale * w0.z, v0.w * scale * w0.w);
    y2[512 + tid * 2] = __floats2half2_rn(v1.x * scale * w1.x, v1.y * scale * w1.y);
    y2[513 + tid * 2] = __floats2half2_rn(v1.z * scale * w1.z, v1.w * scale * w1.w);
}

// ---------------- low-rank gate, stage 1 ----------------
__global__ __launch_bounds__(256) void kg1_k(const __half* __restrict__ xn,
                                             const float* __restrict__ W,
                                             float* __restrict__ t16)
{
    const int gw = (blockIdx.x * 256 + threadIdx.x) >> 5;
    const int lane = threadIdx.x & 31;
    if (gw >= NTOK) return;
    const __half2* xr = (const __half2*)(xn + (size_t)gw * D_MODEL);
    float acc[16];
    #pragma unroll
    for (int j = 0; j < 16; j++) acc[j] = 0.f;
    for (int k2 = lane; k2 < 1024; k2 += 32) {
        const float2 xv = __half22float2(xr[k2]);
        const float4* w0r = (const float4*)(W + (size_t)(2 * k2) * 16);
        const float4* w1r = (const float4*)(W + (size_t)(2 * k2 + 1) * 16);
        float4 A0 = w0r[0], A1 = w0r[1], A2 = w0r[2], A3 = w0r[3];
        float4 B0 = w1r[0], B1 = w1r[1], B2 = w1r[2], B3 = w1r[3];
        acc[0]  = fmaf(xv.x, A0.x, fmaf(xv.y, B0.x, acc[0]));
        acc[1]  = fmaf(xv.x, A0.y, fmaf(xv.y, B0.y, acc[1]));
        acc[2]  = fmaf(xv.x, A0.z, fmaf(xv.y, B0.z, acc[2]));
        acc[3]  = fmaf(xv.x, A0.w, fmaf(xv.y, B0.w, acc[3]));
        acc[4]  = fmaf(xv.x, A1.x, fmaf(xv.y, B1.x, acc[4]));
        acc[5]  = fmaf(xv.x, A1.y, fmaf(xv.y, B1.y, acc[5]));
        acc[6]  = fmaf(xv.x, A1.z, fmaf(xv.y, B1.z, acc[6]));
        acc[7]  = fmaf(xv.x, A1.w, fmaf(xv.y, B1.w, acc[7]));
        acc[8]  = fmaf(xv.x, A2.x, fmaf(xv.y, B2.x, acc[8]));
        acc[9]  = fmaf(xv.x, A2.y, fmaf(xv.y, B2.y, acc[9]));
        acc[10] = fmaf(xv.x, A2.z, fmaf(xv.y, B2.z, acc[10]));
        acc[11] = fmaf(xv.x, A2.w, fmaf(xv.y, B2.w, acc[11]));
        acc[12] = fmaf(xv.x, A3.x, fmaf(xv.y, B3.x, acc[12]));
        acc[13] = fmaf(xv.x, A3.y, fmaf(xv.y, B3.y, acc[13]));
        acc[14] = fmaf(xv.x, A3.z, fmaf(xv.y, B3.z, acc[14]));
        acc[15] = fmaf(xv.x, A3.w, fmaf(xv.y, B3.w, acc[15]));
    }
    #pragma unroll
    for (int j = 0; j < 16; j++) {
        #pragma unroll
        for (int off = 16; off; off >>= 1)
            acc[j] += __shfl_xor_sync(0xffffffffu, acc[j], off);
    }
    if (lane == 0) {
        float4* dst = (float4*)(t16 + (size_t)gw * 16);
        dst[0] = make_float4(acc[0],  acc[1],  acc[2],  acc[3]);
        dst[1] = make_float4(acc[4],  acc[5],  acc[6],  acc[7]);
        dst[2] = make_float4(acc[8],  acc[9],  acc[10], acc[11]);
        dst[3] = make_float4(acc[12], acc[13], acc[14], acc[15]);
    }
}

// ---- stage 2: eg = exp( log_sigmoid(t16 @ Wkg2 + b) / 16 ) ----
__global__ __launch_bounds__(256) void kg2_k(const float* __restrict__ t16,
                                             const float* __restrict__ W,
                                             const float* __restrict__ b,
                                             float* __restrict__ eg)
{
    const size_t idx = (size_t)blockIdx.x * 256 + threadIdx.x;
    const size_t t = idx >> 10;
    const int n = (int)(idx & 1023);
    const float* tr = t16 + t * 16;
    float z = b[n];
    #pragma unroll
    for (int j = 0; j < 16; j++) z = fmaf(tr[j], W[j * 1024 + n], z);
    const float ls = fminf(z, 0.f) - log1pf(__expf(-fabsf(z)));
    eg[idx] = __expf(ls * 0.0625f);
}

// ================ chunked GLA scan: 3 passes ================

// pass 1: per-chunk local state T and gate product P
__global__ __launch_bounds__(256) void scan_p1(const float* __restrict__ qk,
                                               const float* __restrict__ eg,
                                               const float* __restrict__ v,
                                               float* __restrict__ Tc,
                                               float* __restrict__ Pc)
{
    const int bhh = blockIdx.x;
    const int c   = blockIdx.y;
    const int bh = bhh >> 1, half = bhh & 1;
    const int b = bh >> 4, h = bh & 15;
    const int tid = threadIdx.x;
    const int dp = tid >> 2, g = tid & 3;

    __shared__ float sk[2][2][64], se[2][2][64], sv[2][2][64];
    float S[16], pe[16];
    #pragma unroll
    for (int j = 0; j < 16; j++) { S[j] = 0.f; pe[j] = 1.f; }

    const size_t tok0 = (size_t)b * LSEQ + (size_t)c * CLEN;
    const int i64 = tid & 63;
    const int sel = tid >> 6;

    auto loadslot = [&](int slot, int t0) {
        #pragma unroll
        for (int sub = 0; sub < 2; sub++) {
            const size_t base = tok0 + t0 + sub;
            if (sel == 1)      sk[slot][sub][i64] = qk[base * 2048 + 1024 + h * 64 + i64];
            else if (sel == 2) se[slot][sub][i64] = eg[base * 1024 + h * 64 + i64];
            else if (sel == 3) sv[slot][sub][i64] = v [base * 2048 + h * 128 + half * 64 + i64];
        }
    };

    loadslot(0, 0);
    __syncthreads();
    for (int t = 0; t < CLEN; t += 2) {
        const int p = (t >> 1) & 1;
        if (t + 2 < CLEN) loadslot(p ^ 1, t + 2);
        #pragma unroll
        for (int sub = 0; sub < 2; sub++) {
            const float vv = sv[p][sub][dp];
            #pragma unroll
            for (int j = 0; j < 16; j++) {
                const int kk = g * 16 + j;
                const float e = se[p][sub][kk];
                S[j]  = fmaf(S[j], e, sk[p][sub][kk] * vv);
                pe[j] *= e;
            }
        }
        __syncthreads();
    }

    const size_t tb = (((size_t)c * 64 + bhh) * 64 + dp) * 64 + g * 16;
    #pragma unroll
    for (int j = 0; j < 16; j++) Tc[tb + j] = S[j];
    if (dp == 0) {
        const size_t pb = ((size_t)c * 64 + bhh) * 64 + g * 16;
        #pragma unroll
        for (int j = 0; j < 16; j++) Pc[pb + j] = pe[j];
    }
}

// pass 2: sequential chunk combine
__global__ __launch_bounds__(256) void scan_p2(const float* __restrict__ Tc,
                                               const float* __restrict__ Pc,
                                               float* __restrict__ Sst)
{
    const int bhh = blockIdx.x;
    const int tid = threadIdx.x;
    const int dp = tid >> 2, g = tid & 3;
    float S[16];
    #pragma unroll
    for (int j = 0; j < 16; j++) S[j] = 0.f;
    for (int c = 0; c < NCHUNK; c++) {
        const size_t tb = (((size_t)c * 64 + bhh) * 64 + dp) * 64 + g * 16;
        const size_t pb = ((size_t)c * 64 + bhh) * 64 + g * 16;
        #pragma unroll
        for (int j = 0; j < 16; j++) Sst[tb + j] = S[j];
        #pragma unroll
        for (int j = 0; j < 16; j++) S[j] = fmaf(Pc[pb + j], S[j], Tc[tb + j]);
    }
}

// pass 3: replay chunks from entry state, emit o (+ Sf on last chunk)
__global__ __launch_bounds__(256) void scan_p3(const float* __restrict__ qk,
                                               const float* __restrict__ eg,
                                               const float* __restrict__ v,
                                               const float* __restrict__ Sst,
                                               float* __restrict__ o,
                                               float* __restrict__ Sf)
{
    const int bhh = blockIdx.x;
    const int c   = blockIdx.y;
    const int bh = bhh >> 1, half = bhh & 1;
    const int b = bh >> 4, h = bh & 15;
    const int tid = threadIdx.x;
    const int dp = tid >> 2, g = tid & 3;

    __shared__ float sq[2][2][64], sk[2][2][64], se[2][2][64], sv[2][2][64];
    float S[16];
    {
        const size_t tb = (((size_t)c * 64 + bhh) * 64 + dp) * 64 + g * 16;
        #pragma unroll
        for (int j = 0; j < 16; j++) S[j] = Sst[tb + j];
    }

    const size_t tok0 = (size_t)b * LSEQ + (size_t)c * CLEN;
    const int i64 = tid & 63;
    const int sel = tid >> 6;

    auto loadslot = [&](int slot, int t0) {
        #pragma unroll
        for (int sub = 0; sub < 2; sub++) {
            const size_t base = tok0 + t0 + sub;
            if (sel == 0)      sq[slot][sub][i64] = qk[base * 2048 + h * 64 + i64];
            else if (sel == 1) sk[slot][sub][i64] = qk[base * 2048 + 1024 + h * 64 + i64];
            else if (sel == 2) se[slot][sub][i64] = eg[base * 1024 + h * 64 + i64];
            else               sv[slot][sub][i64] = v [base * 2048 + h * 128 + half * 64 + i64];
        }
    };

    loadslot(0, 0);
    __syncthreads();
    for (int t = 0; t < CLEN; t += 2) {
        const int p = (t >> 1) & 1;
        if (t + 2 < CLEN) loadslot(p ^ 1, t + 2);
        #pragma unroll
        for (int sub = 0; sub < 2; sub++) {
            const float vv = sv[p][sub][dp];
            float acc = 0.f;
            #pragma unroll
            for (int j = 0; j < 16; j++) {
                const int kk = g * 16 + j;
                S[j] = fmaf(S[j], se[p][sub][kk], sk[p][sub][kk] * vv);
                acc  = fmaf(sq[p][sub][kk], S[j], acc);
            }
            acc += __shfl_xor_sync(0xffffffffu, acc, 1);
            acc += __shfl_xor_sync(0xffffffffu, acc, 2);
            if (g == 0)
                o[(tok0 + t + sub) * 2048 + h * 128 + half * 64 + dp] = acc;
        }
        __syncthreads();
    }

    if (c == NCHUNK - 1 && Sf) {
        #pragma unroll
        for (int j = 0; j < 16; j++) {
            const int kk = g * 16 + j;
            Sf[(((size_t)b * 16 + h) * 64 + kk) * 128 + half * 64 + dp] = S[j];
        }
    }
}

// ------- group-norm + silu(g) gate; fp32 in -> half out -------
__global__ __launch_bounds__(256) void gnorm_silu_k(const float* __restrict__ o,
                                                    const float* __restrict__ g,
                                                    __half* __restrict__ oh)
{
    const int wid  = (blockIdx.x * 256 + threadIdx.x) >> 5;
    const int lane = threadIdx.x & 31;
    const int tk = wid >> 4, h = wid & 15;
    const size_t base = (size_t)tk * 2048 + (size_t)h * 128;
    float4 ov = *(const float4*)(o + base + lane * 4);
    float s  = ov.x + ov.y + ov.z + ov.w;
    float ss = ov.x*ov.x + ov.y*ov.y + ov.z*ov.z + ov.w*ov.w;
    #pragma unroll
    for (int off = 16; off; off >>= 1) {
        s  += __shfl_xor_sync(0xffffffffu, s,  off);
        ss += __shfl_xor_sync(0xffffffffu, ss, off);
    }
    const float mu = s * (1.f / 128.f);
    const float rs = rsqrtf(ss * (1.f / 128.f) - mu * mu + 1e-5f);
    float4 gv = *(const float4*)(g + base + lane * 4);
    __half2* op = (__half2*)(oh + base + lane * 4);
    op[0] = __floats2half2_rn(siluf(gv.x) * ((ov.x - mu) * rs),
                              siluf(gv.y) * ((ov.y - mu) * rs));
    op[1] = __floats2half2_rn(siluf(gv.z) * ((ov.z - mu) * rs),
                              siluf(gv.w) * ((ov.w - mu) * rs));
}

// ---------------- launch ----------------
extern "C" void kernel_launch(void* const* d_in, const int* in_sizes, int n_in,
                              void* d_out, int out_size)
{
    (void)in_sizes; (void)n_in;
    const float* x    = (const float*)d_in[0];
    const float* Wq   = (const float*)d_in[1];
    const float* Wk   = (const float*)d_in[2];
    const float* Wkg1 = (const float*)d_in[3];
    const float* Wkg2 = (const float*)d_in[4];
    const float* bkg2 = (const float*)d_in[5];
    const float* Wv   = (const float*)d_in[6];
    const float* Wg   = (const float*)d_in[7];
    const float* bg   = (const float*)d_in[8];
    const float* Wo   = (const float*)d_in[9];
    const float* ln1  = (const float*)d_in[10];
    const float* ln2  = (const float*)d_in[11];
    const float* W1   = (const float*)d_in[12];
    const float* W3   = (const float*)d_in[13];
    const float* W2   = (const float*)d_in[14];
    float* out = (float*)d_out;

    __half *xn, *oh, *h1h, *wt;
    float *qk, *egb, *t16, *vb, *gb, *ob, *x2, *Tc, *Pc, *Sst;
    cudaGetSymbolAddress((void**)&xn,  g_xn);
    cudaGetSymbolAddress((void**)&qk,  g_qk);
    cudaGetSymbolAddress((void**)&egb, g_eg);
    cudaGetSymbolAddress((void**)&t16, g_t16);
    cudaGetSymbolAddress((void**)&vb,  g_v);
    cudaGetSymbolAddress((void**)&gb,  g_gt);
    cudaGetSymbolAddress((void**)&ob,  g_o);
    cudaGetSymbolAddress((void**)&oh,  g_oh);
    cudaGetSymbolAddress((void**)&x2,  g_x2);
    cudaGetSymbolAddress((void**)&h1h, g_h1h);
    cudaGetSymbolAddress((void**)&wt,  g_wt);
    cudaGetSymbolAddress((void**)&Tc,  g_Tc);
    cudaGetSymbolAddress((void**)&Pc,  g_Pc);
    cudaGetSymbolAddress((void**)&Sst, g_Sst);

    __half* wqkvgT = wt;                           // [6144][2048]
    __half* woT    = wqkvgT + (size_t)6144 * 2048;
    __half* w13T   = woT    + (size_t)2048 * 2048; // [11264][2048] interleaved
    __half* w2T    = w13T   + (size_t)11264 * 2048;

    cudaFuncSetAttribute(gemm_h<EPI_QKVG  >, cudaFuncAttributeMaxDynamicSharedMemorySize, GSMEM);
    cudaFuncSetAttribute(gemm_h<EPI_RES   >, cudaFuncAttributeMaxDynamicSharedMemorySize, GSMEM);
    cudaFuncSetAttribute(gemm_h<EPI_SWIGLU>, cudaFuncAttributeMaxDynamicSharedMemorySize, GSMEM);

    const size_t xElems  = (size_t)NTOK * D_MODEL;
    const size_t sfElems = (size_t)BDIM * NHEAD * 64 * 128;
    float* Sf = ((size_t)out_size >= xElems + sfElems) ? (out + xElems) : nullptr;

    const float kscale = 0.08838834764831843f;

    transpose_h<<<dim3(32,  64), 256>>>(Wq, wqkvgT,                     2048, 1024, 1.f,    1, 0);
    transpose_h<<<dim3(32,  64), 256>>>(Wk, wqkvgT + (size_t)1024*2048, 2048, 1024, kscale, 1, 0);
    transpose_h<<<dim3(64,  64), 256>>>(Wv, wqkvgT + (size_t)2048*2048, 2048, 2048, 1.f,    1, 0);
    transpose_h<<<dim3(64,  64), 256>>>(Wg, wqkvgT + (size_t)4096*2048, 2048, 2048, 1.f,    1, 0);
    transpose_h<<<dim3(64,  64), 256>>>(Wo, woT,  2048, 2048, 1.f, 1, 0);
    transpose_h<<<dim3(176, 64), 256>>>(W1, w13T, 2048, 5632, 1.f, 2, 0);
    transpose_h<<<dim3(176, 64), 256>>>(W3, w13T, 2048, 5632, 1.f, 2, 1);
    transpose_h<<<dim3(64, 176), 256>>>(W2, w2T,  5632, 2048, 1.f, 1, 0);

    rmsnorm_k<<<NTOK, 256>>>(x, ln1, xn);

    gemm_h<EPI_QKVG><<<dim3(48, 64), 128, GSMEM>>>(
        xn, wqkvgT, qk, NTOK, 6144, 2048, bg, vb, gb);

    kg1_k<<<NTOK / 8, 256>>>(xn, Wkg1, t16);
    kg2_k<<<(NTOK * 1024) / 256, 256>>>(t16, Wkg2, bkg2, egb);

    scan_p1<<<dim3(64, NCHUNK), 256>>>(qk, egb, vb, Tc, Pc);
    scan_p2<<<64, 256>>>(Tc, Pc, Sst);
    scan_p3<<<dim3(64, NCHUNK), 256>>>(qk, egb, vb, Sst, ob, Sf);

    gnorm_silu_k<<<(NTOK * NHEAD) / 8, 256>>>(ob, gb, oh);

    gemm_h<EPI_RES><<<dim3(16, 64), 128, GSMEM>>>(
        oh, woT, x2, NTOK, 2048, 2048, nullptr, x, nullptr);

    rmsnorm_k<<<NTOK, 256>>>(x2, ln2, xn);

    gemm_h<EPI_SWIGLU><<<dim3(88, 64), 128, GSMEM>>>(
        xn, w13T, h1h, NTOK, 11264, 2048, nullptr, nullptr, nullptr);

    gemm_h<EPI_RES><<<dim3(16, 64), 128, GSMEM>>>(
        h1h, w2T, out, NTOK, D_MODEL, HIDDEN, nullptr, x2, nullptr);
}

// round 9
// speedup vs baseline: 1.5475x; 1.5475x over previous
#include <cuda_runtime.h>
#include <cuda_fp16.h>
#include <cstdint>
#include <cstddef>

#define D_MODEL 2048
#define LSEQ    4096
#define BDIM    2
#define NTOK    (BDIM * LSEQ)      // 8192
#define NHEAD   16
#define HIDDEN  5632
#define NCHUNK  32
#define CLEN    (LSEQ / NCHUNK)    // 128

// ---------------- scratch (device globals; no allocation allowed) ----------------
__device__ __half g_xn [(size_t)NTOK * D_MODEL];
__device__ float  g_qk [(size_t)NTOK * 2048];             // q | k*scale
__device__ float  g_eg [(size_t)NTOK * 1024];
__device__ float  g_t16[(size_t)NTOK * 16];
__device__ float  g_v  [(size_t)NTOK * D_MODEL];
__device__ float  g_gt [(size_t)NTOK * D_MODEL];
__device__ float  g_o  [(size_t)NTOK * D_MODEL];
__device__ __half g_oh [(size_t)NTOK * D_MODEL];
__device__ float  g_x2 [(size_t)NTOK * D_MODEL];
__device__ __half g_h1h[(size_t)NTOK * HIDDEN];
__device__ __half g_wt [51380224];
__device__ float  g_Tc [(size_t)NCHUNK * 64 * 64 * 64];   // per-chunk local state
__device__ float  g_Pc [(size_t)NCHUNK * 64 * 64];        // per-chunk gate product
__device__ float  g_Sst[(size_t)NCHUNK * 64 * 64 * 64];   // state entering chunk

__device__ __forceinline__ float siluf(float x) { return x / (1.f + __expf(-x)); }
__device__ __forceinline__ void cpa16(void* s, const void* g) {
    uint32_t a = (uint32_t)__cvta_generic_to_shared(s);
    asm volatile("cp.async.cg.shared.global [%0], [%1], 16;" :: "r"(a), "l"(g));
}

// ================= fp16 tensor-core GEMM =================
// C[M,N] = epi(A[M,K] @ Wt[N,K]^T). CTA 128x128, 128 threads, 4 warps (2m x 2n),
// warp tile 64x64. BK=64, 3 stages, 2 CTAs/SM.
enum { EPI_QKVG = 0, EPI_RES = 3, EPI_SWIGLU = 5 };

#define BK    64
#define LDH   72                           // halves/row: 144B (16B-aligned, ldsm conflict-free)
#define AH    (128 * LDH)                  // 9216 halves
#define STGH  (2 * AH)                     // A + B
#define NST   3
#define GSMEM (NST * STGH * 2)             // 110592 B

#define LDSM4(r, a)                                                            \
    asm volatile("ldmatrix.sync.aligned.m8n8.x4.shared.b16 {%0,%1,%2,%3}, [%4];" \
        : "=r"((r)[0]), "=r"((r)[1]), "=r"((r)[2]), "=r"((r)[3]) : "r"(a))

__device__ __forceinline__ void mma_h(float* c, const uint32_t* a, const uint32_t* b) {
    asm volatile(
        "mma.sync.aligned.m16n8k16.row.col.f32.f16.f16.f32 "
        "{%0,%1,%2,%3}, {%4,%5,%6,%7}, {%8,%9}, {%0,%1,%2,%3};"
        : "+f"(c[0]), "+f"(c[1]), "+f"(c[2]), "+f"(c[3])
        : "r"(a[0]), "r"(a[1]), "r"(a[2]), "r"(a[3]), "r"(b[0]), "r"(b[1]));
}

template <int EPI>
__global__ __launch_bounds__(128, 2) void gemm_h(
    const __half* __restrict__ A, const __half* __restrict__ Wt, void* __restrict__ Cv,
    int M, int N, int K,
    const float* __restrict__ bias, const float* __restrict__ res,
    const float* __restrict__ aux)
{
    extern __shared__ __align__(16) __half hsm[];
    const int tid = threadIdx.x;
    const int wid = tid >> 5, lane = tid & 31;
    const int g = lane >> 2, tig = lane & 3;
    const int wm = (wid >> 1) * 64;
    const int wn = (wid & 1) * 64;
    const int m0 = blockIdx.y * 128;
    const int n0 = blockIdx.x * 128;
    const int nK = K >> 6;

    auto load_stage = [&](int slot, int kc) {
        __half* As = hsm + slot * STGH;
        __half* Bs = As + AH;
        const int k0 = kc * BK;
        const __half* Ag = A  + (size_t)m0 * K + k0;
        const __half* Bg = Wt + (size_t)n0 * K + k0;
        #pragma unroll
        for (int j = 0; j < 8; j++) {          // 1024 chunks each for A and B
            const int i = tid + j * 128;
            const int row = i >> 3, c = i & 7;
            cpa16(As + row * LDH + c * 8, Ag + (size_t)row * K + c * 8);
            cpa16(Bs + row * LDH + c * 8, Bg + (size_t)row * K + c * 8);
        }
        asm volatile("cp.async.commit_group;");
    };

    float acc[4][8][4];
    #pragma unroll
    for (int mt = 0; mt < 4; mt++)
        #pragma unroll
        for (int nt = 0; nt < 8; nt++)
            #pragma unroll
            for (int r = 0; r < 4; r++) acc[mt][nt][r] = 0.f;

    load_stage(0, 0);
    load_stage(1, 1);

    const uint32_t sbase = (uint32_t)__cvta_generic_to_shared(hsm);
    const int lrA = lane & 15;
    const int lkA = (lane >> 4) << 3;
    const int rB  = (lane & 7) + ((lane & 16) ? 8 : 0);
    const int lkB = (lane & 8) ? 8 : 0;

    for (int ks = 0; ks < nK; ks++) {
        const int slot = ks % 3;
        if (ks + 1 < nK) asm volatile("cp.async.wait_group 1;");
        else             asm volatile("cp.async.wait_group 0;");
        __syncthreads();
        if (ks + 2 < nK) load_stage((ks + 2) % 3, ks + 2);

        const uint32_t aB = sbase + (uint32_t)(slot * STGH) * 2;
        const uint32_t bB = aB + AH * 2;
        const uint32_t aAddr = aB + (uint32_t)((wm + lrA) * LDH + lkA) * 2;
        const uint32_t bAddr = bB + (uint32_t)((wn + rB) * LDH + lkB) * 2;

        #pragma unroll
        for (int kstep = 0; kstep < 4; kstep++) {
            uint32_t a[4][4], b[4][4];
            #pragma unroll
            for (int mt = 0; mt < 4; mt++)
                LDSM4(a[mt], aAddr + (uint32_t)(mt * 16 * LDH) * 2 + kstep * 32);
            #pragma unroll
            for (int np = 0; np < 4; np++)
                LDSM4(b[np], bAddr + (uint32_t)(np * 16 * LDH) * 2 + kstep * 32);
            #pragma unroll
            for (int mt = 0; mt < 4; mt++)
                #pragma unroll
                for (int nt = 0; nt < 8; nt++)
                    mma_h(acc[mt][nt], a[mt], &b[nt >> 1][(nt & 1) * 2]);
        }
    }

    // ---- epilogue ----
    #pragma unroll
    for (int mt = 0; mt < 4; mt++) {
        #pragma unroll
        for (int hf = 0; hf < 2; hf++) {
            const size_t row = (size_t)m0 + wm + mt * 16 + g + hf * 8;
            #pragma unroll
            for (int nt = 0; nt < 8; nt++) {
                const int col = n0 + wn + nt * 8 + tig * 2;
                float v0 = acc[mt][nt][hf * 2 + 0];
                float v1 = acc[mt][nt][hf * 2 + 1];
                if (EPI == EPI_QKVG) {
                    // regions: [0,2048)=qk  [2048,4096)=v  [4096,6144)=g(+bias)
                    float* dst;
                    int cl = col;
                    if (n0 < 2048)      { dst = (float*)Cv; }
                    else if (n0 < 4096) { dst = (float*)res; cl -= 2048; }
                    else {
                        dst = (float*)aux; cl -= 4096;
                        v0 += bias[cl]; v1 += bias[cl + 1];
                    }
                    *(float2*)(dst + row * 2048 + cl) = make_float2(v0, v1);
                } else if (EPI == EPI_RES) {
                    const size_t base = row * (size_t)N + col;
                    const float2 rv = *(const float2*)(res + base);
                    *(float2*)((float*)Cv + base) = make_float2(v0 + rv.x, v1 + rv.y);
                } else { // EPI_SWIGLU
                    ((__half*)Cv)[row * (size_t)(N >> 1) + (col >> 1)] =
                        __float2half_rn(siluf(v0) * v1);
                }
            }
        }
    }
}

// ------- 32x32 tiled transpose + fp16 convert; out row = c*rowMul + rowOff -------
__global__ __launch_bounds__(256) void transpose_h(const float* __restrict__ in,
                                                   __half* __restrict__ out,
                                                   int R, int Ccols, float scale,
                                                   int rowMul, int rowOff)
{
    __shared__ float tile[32][33];
    const int c0 = blockIdx.x * 32, r0 = blockIdx.y * 32;
    const int x = threadIdx.x & 31, y = threadIdx.x >> 5;
    #pragma unroll
    for (int i = 0; i < 32; i += 8)
        tile[y + i][x] = in[(size_t)(r0 + y + i) * Ccols + c0 + x] * scale;
    __syncthreads();
    #pragma unroll
    for (int i = 0; i < 32; i += 8)
        out[((size_t)(c0 + y + i) * rowMul + rowOff) * R + r0 + x] =
            __float2half_rn(tile[x][y + i]);
}

// ---------------- RMSNorm: fp32 in -> half out ----------------
__global__ __launch_bounds__(256) void rmsnorm_k(const float* __restrict__ x,
                                                 const float* __restrict__ w,
                                                 __half* __restrict__ y)
{
    const int row = blockIdx.x;
    const int tid = threadIdx.x;
    const float4* xr = (const float4*)(x + (size_t)row * D_MODEL);
    float4 v0 = xr[tid];
    float4 v1 = xr[tid + 256];
    float ss = v0.x*v0.x + v0.y*v0.y + v0.z*v0.z + v0.w*v0.w
             + v1.x*v1.x + v1.y*v1.y + v1.z*v1.z + v1.w*v1.w;
    #pragma unroll
    for (int off = 16; off; off >>= 1) ss += __shfl_xor_sync(0xffffffffu, ss, off);
    __shared__ float red[8];
    if ((tid & 31) == 0) red[tid >> 5] = ss;
    __syncthreads();
    if (tid < 32) {
        float t = (tid < 8) ? red[tid] : 0.f;
        #pragma unroll
        for (int off = 4; off; off >>= 1) t += __shfl_xor_sync(0xffffffffu, t, off);
        if (tid == 0) red[0] = t;
    }
    __syncthreads();
    const float scale = rsqrtf(red[0] * (1.f / (float)D_MODEL) + 1e-5f);
    const float4* wr = (const float4*)w;
    float4 w0 = wr[tid], w1 = wr[tid + 256];
    __half2* y2 = (__half2*)(y + (size_t)row * D_MODEL);
    y2[tid * 2]       = __floats2half2_rn(v0.x * scale * w0.x, v0.y * scale * w0.y);
    y2[tid * 2 + 1]   = __floats2half2_rn(v0.z * scale * w0.z, v0.w * scale * w0.w);
    y2[512 + tid * 2] = __floats2half2_rn(v1.x * scale * w1.x, v1.y * scale * w1.y);
    y2[513 + tid * 2] = __floats2half2_rn(v1.z * scale * w1.z, v1.w * scale * w1.w);
}

// ---------------- low-rank gate, stage 1 ----------------
__global__ __launch_bounds__(256) void kg1_k(const __half* __restrict__ xn,
                                             const float* __restrict__ W,
                                             float* __restrict__ t16)
{
    const int gw = (blockIdx.x * 256 + threadIdx.x) >> 5;
    const int lane = threadIdx.x & 31;
    if (gw >= NTOK) return;
    const __half2* xr = (const __half2*)(xn + (size_t)gw * D_MODEL);
    float acc[16];
    #pragma unroll
    for (int j = 0; j < 16; j++) acc[j] = 0.f;
    for (int k2 = lane; k2 < 1024; k2 += 32) {
        const float2 xv = __half22float2(xr[k2]);
        const float4* w0r = (const float4*)(W + (size_t)(2 * k2) * 16);
        const float4* w1r = (const float4*)(W + (size_t)(2 * k2 + 1) * 16);
        float4 A0 = w0r[0], A1 = w0r[1], A2 = w0r[2], A3 = w0r[3];
        float4 B0 = w1r[0], B1 = w1r[1], B2 = w1r[2], B3 = w1r[3];
        acc[0]  = fmaf(xv.x, A0.x, fmaf(xv.y, B0.x, acc[0]));
        acc[1]  = fmaf(xv.x, A0.y, fmaf(xv.y, B0.y, acc[1]));
        acc[2]  = fmaf(xv.x, A0.z, fmaf(xv.y, B0.z, acc[2]));
        acc[3]  = fmaf(xv.x, A0.w, fmaf(xv.y, B0.w, acc[3]));
        acc[4]  = fmaf(xv.x, A1.x, fmaf(xv.y, B1.x, acc[4]));
        acc[5]  = fmaf(xv.x, A1.y, fmaf(xv.y, B1.y, acc[5]));
        acc[6]  = fmaf(xv.x, A1.z, fmaf(xv.y, B1.z, acc[6]));
        acc[7]  = fmaf(xv.x, A1.w, fmaf(xv.y, B1.w, acc[7]));
        acc[8]  = fmaf(xv.x, A2.x, fmaf(xv.y, B2.x, acc[8]));
        acc[9]  = fmaf(xv.x, A2.y, fmaf(xv.y, B2.y, acc[9]));
        acc[10] = fmaf(xv.x, A2.z, fmaf(xv.y, B2.z, acc[10]));
        acc[11] = fmaf(xv.x, A2.w, fmaf(xv.y, B2.w, acc[11]));
        acc[12] = fmaf(xv.x, A3.x, fmaf(xv.y, B3.x, acc[12]));
        acc[13] = fmaf(xv.x, A3.y, fmaf(xv.y, B3.y, acc[13]));
        acc[14] = fmaf(xv.x, A3.z, fmaf(xv.y, B3.z, acc[14]));
        acc[15] = fmaf(xv.x, A3.w, fmaf(xv.y, B3.w, acc[15]));
    }
    #pragma unroll
    for (int j = 0; j < 16; j++) {
        #pragma unroll
        for (int off = 16; off; off >>= 1)
            acc[j] += __shfl_xor_sync(0xffffffffu, acc[j], off);
    }
    if (lane == 0) {
        float4* dst = (float4*)(t16 + (size_t)gw * 16);
        dst[0] = make_float4(acc[0],  acc[1],  acc[2],  acc[3]);
        dst[1] = make_float4(acc[4],  acc[5],  acc[6],  acc[7]);
        dst[2] = make_float4(acc[8],  acc[9],  acc[10], acc[11]);
        dst[3] = make_float4(acc[12], acc[13], acc[14], acc[15]);
    }
}

// ---- stage 2: eg = exp( log_sigmoid(t16 @ Wkg2 + b) / 16 ) ----
__global__ __launch_bounds__(256) void kg2_k(const float* __restrict__ t16,
                                             const float* __restrict__ W,
                                             const float* __restrict__ b,
                                             float* __restrict__ eg)
{
    const size_t idx = (size_t)blockIdx.x * 256 + threadIdx.x;
    const size_t t = idx >> 10;
    const int n = (int)(idx & 1023);
    const float* tr = t16 + t * 16;
    float z = b[n];
    #pragma unroll
    for (int j = 0; j < 16; j++) z = fmaf(tr[j], W[j * 1024 + n], z);
    const float ls = fminf(z, 0.f) - log1pf(__expf(-fabsf(z)));
    eg[idx] = __expf(ls * 0.0625f);
}

// ================ chunked GLA scan: 3 passes ================

// pass 1: per-chunk local state T and gate product P
__global__ __launch_bounds__(256) void scan_p1(const float* __restrict__ qk,
                                               const float* __restrict__ eg,
                                               const float* __restrict__ v,
                                               float* __restrict__ Tc,
                                               float* __restrict__ Pc)
{
    const int bhh = blockIdx.x;
    const int c   = blockIdx.y;
    const int bh = bhh >> 1, half = bhh & 1;
    const int b = bh >> 4, h = bh & 15;
    const int tid = threadIdx.x;
    const int dp = tid >> 2, g = tid & 3;

    __shared__ float sk[2][2][64], se[2][2][64], sv[2][2][64];
    float S[16], pe[16];
    #pragma unroll
    for (int j = 0; j < 16; j++) { S[j] = 0.f; pe[j] = 1.f; }

    const size_t tok0 = (size_t)b * LSEQ + (size_t)c * CLEN;
    const int i64 = tid & 63;
    const int sel = tid >> 6;

    auto loadslot = [&](int slot, int t0) {
        #pragma unroll
        for (int sub = 0; sub < 2; sub++) {
            const size_t base = tok0 + t0 + sub;
            if (sel == 1)      sk[slot][sub][i64] = qk[base * 2048 + 1024 + h * 64 + i64];
            else if (sel == 2) se[slot][sub][i64] = eg[base * 1024 + h * 64 + i64];
            else if (sel == 3) sv[slot][sub][i64] = v [base * 2048 + h * 128 + half * 64 + i64];
        }
    };

    loadslot(0, 0);
    __syncthreads();
    for (int t = 0; t < CLEN; t += 2) {
        const int p = (t >> 1) & 1;
        if (t + 2 < CLEN) loadslot(p ^ 1, t + 2);
        #pragma unroll
        for (int sub = 0; sub < 2; sub++) {
            const float vv = sv[p][sub][dp];
            #pragma unroll
            for (int j = 0; j < 16; j++) {
                const int kk = g * 16 + j;
                const float e = se[p][sub][kk];
                S[j]  = fmaf(S[j], e, sk[p][sub][kk] * vv);
                pe[j] *= e;
            }
        }
        __syncthreads();
    }

    const size_t tb = (((size_t)c * 64 + bhh) * 64 + dp) * 64 + g * 16;
    #pragma unroll
    for (int j = 0; j < 16; j++) Tc[tb + j] = S[j];
    if (dp == 0) {
        const size_t pb = ((size_t)c * 64 + bhh) * 64 + g * 16;
        #pragma unroll
        for (int j = 0; j < 16; j++) Pc[pb + j] = pe[j];
    }
}

// pass 2: sequential chunk combine
__global__ __launch_bounds__(256) void scan_p2(const float* __restrict__ Tc,
                                               const float* __restrict__ Pc,
                                               float* __restrict__ Sst)
{
    const int bhh = blockIdx.x;
    const int tid = threadIdx.x;
    const int dp = tid >> 2, g = tid & 3;
    float S[16];
    #pragma unroll
    for (int j = 0; j < 16; j++) S[j] = 0.f;
    for (int c = 0; c < NCHUNK; c++) {
        const size_t tb = (((size_t)c * 64 + bhh) * 64 + dp) * 64 + g * 16;
        const size_t pb = ((size_t)c * 64 + bhh) * 64 + g * 16;
        #pragma unroll
        for (int j = 0; j < 16; j++) Sst[tb + j] = S[j];
        #pragma unroll
        for (int j = 0; j < 16; j++) S[j] = fmaf(Pc[pb + j], S[j], Tc[tb + j]);
    }
}

// pass 3: replay chunks from entry state, emit o (+ Sf on last chunk)
__global__ __launch_bounds__(256) void scan_p3(const float* __restrict__ qk,
                                               const float* __restrict__ eg,
                                               const float* __restrict__ v,
                                               const float* __restrict__ Sst,
                                               float* __restrict__ o,
                                               float* __restrict__ Sf)
{
    const int bhh = blockIdx.x;
    const int c   = blockIdx.y;
    const int bh = bhh >> 1, half = bhh & 1;
    const int b = bh >> 4, h = bh & 15;
    const int tid = threadIdx.x;
    const int dp = tid >> 2, g = tid & 3;

    __shared__ float sq[2][2][64], sk[2][2][64], se[2][2][64], sv[2][2][64];
    float S[16];
    {
        const size_t tb = (((size_t)c * 64 + bhh) * 64 + dp) * 64 + g * 16;
        #pragma unroll
        for (int j = 0; j < 16; j++) S[j] = Sst[tb + j];
    }

    const size_t tok0 = (size_t)b * LSEQ + (size_t)c * CLEN;
    const int i64 = tid & 63;
    const int sel = tid >> 6;

    auto loadslot = [&](int slot, int t0) {
        #pragma unroll
        for (int sub = 0; sub < 2; sub++) {
            const size_t base = tok0 + t0 + sub;
            if (sel == 0)      sq[slot][sub][i64] = qk[base * 2048 + h * 64 + i64];
            else if (sel == 1) sk[slot][sub][i64] = qk[base * 2048 + 1024 + h * 64 + i64];
            else if (sel == 2) se[slot][sub][i64] = eg[base * 1024 + h * 64 + i64];
            else               sv[slot][sub][i64] = v [base * 2048 + h * 128 + half * 64 + i64];
        }
    };

    loadslot(0, 0);
    __syncthreads();
    for (int t = 0; t < CLEN; t += 2) {
        const int p = (t >> 1) & 1;
        if (t + 2 < CLEN) loadslot(p ^ 1, t + 2);
        #pragma unroll
        for (int sub = 0; sub < 2; sub++) {
            const float vv = sv[p][sub][dp];
            float acc = 0.f;
            #pragma unroll
            for (int j = 0; j < 16; j++) {
                const int kk = g * 16 + j;
                S[j] = fmaf(S[j], se[p][sub][kk], sk[p][sub][kk] * vv);
                acc  = fmaf(sq[p][sub][kk], S[j], acc);
            }
            acc += __shfl_xor_sync(0xffffffffu, acc, 1);
            acc += __shfl_xor_sync(0xffffffffu, acc, 2);
            if (g == 0)
                o[(tok0 + t + sub) * 2048 + h * 128 + half * 64 + dp] = acc;
        }
        __syncthreads();
    }

    if (c == NCHUNK - 1 && Sf) {
        #pragma unroll
        for (int j = 0; j < 16; j++) {
            const int kk = g * 16 + j;
            Sf[(((size_t)b * 16 + h) * 64 + kk) * 128 + half * 64 + dp] = S[j];
        }
    }
}

// ------- group-norm + silu(g) gate; fp32 in -> half out -------
__global__ __launch_bounds__(256) void gnorm_silu_k(const float* __restrict__ o,
                                                    const float* __restrict__ g,
                                                    __half* __restrict__ oh)
{
    const int wid  = (blockIdx.x * 256 + threadIdx.x) >> 5;
    const int lane = threadIdx.x & 31;
    const int tk = wid >> 4, h = wid & 15;
    const size_t base = (size_t)tk * 2048 + (size_t)h * 128;
    float4 ov = *(const float4*)(o + base + lane * 4);
    float s  = ov.x + ov.y + ov.z + ov.w;
    float ss = ov.x*ov.x + ov.y*ov.y + ov.z*ov.z + ov.w*ov.w;
    #pragma unroll
    for (int off = 16; off; off >>= 1) {
        s  += __shfl_xor_sync(0xffffffffu, s,  off);
        ss += __shfl_xor_sync(0xffffffffu, ss, off);
    }
    const float mu = s * (1.f / 128.f);
    const float rs = rsqrtf(ss * (1.f / 128.f) - mu * mu + 1e-5f);
    float4 gv = *(const float4*)(g + base + lane * 4);
    __half2* op = (__half2*)(oh + base + lane * 4);
    op[0] = __floats2half2_rn(siluf(gv.x) * ((ov.x - mu) * rs),
                              siluf(gv.y) * ((ov.y - mu) * rs));
    op[1] = __floats2half2_rn(siluf(gv.z) * ((ov.z - mu) * rs),
                              siluf(gv.w) * ((ov.w - mu) * rs));
}

// ---------------- launch ----------------
extern "C" void kernel_launch(void* const* d_in, const int* in_sizes, int n_in,
                              void* d_out, int out_size)
{
    (void)in_sizes; (void)n_in;
    const float* x    = (const float*)d_in[0];
    const float* Wq   = (const float*)d_in[1];
    const float* Wk   = (const float*)d_in[2];
    const float* Wkg1 = (const float*)d_in[3];
    const float* Wkg2 = (const float*)d_in[4];
    const float* bkg2 = (const float*)d_in[5];
    const float* Wv   = (const float*)d_in[6];
    const float* Wg   = (const float*)d_in[7];
    const float* bg   = (const float*)d_in[8];
    const float* Wo   = (const float*)d_in[9];
    const float* ln1  = (const float*)d_in[10];
    const float* ln2  = (const float*)d_in[11];
    const float* W1   = (const float*)d_in[12];
    const float* W3   = (const float*)d_in[13];
    const float* W2   = (const float*)d_in[14];
    float* out = (float*)d_out;

    __half *xn, *oh, *h1h, *wt;
    float *qk, *egb, *t16, *vb, *gb, *ob, *x2, *Tc, *Pc, *Sst;
    cudaGetSymbolAddress((void**)&xn,  g_xn);
    cudaGetSymbolAddress((void**)&qk,  g_qk);
    cudaGetSymbolAddress((void**)&egb, g_eg);
    cudaGetSymbolAddress((void**)&t16, g_t16);
    cudaGetSymbolAddress((void**)&vb,  g_v);
    cudaGetSymbolAddress((void**)&gb,  g_gt);
    cudaGetSymbolAddress((void**)&ob,  g_o);
    cudaGetSymbolAddress((void**)&oh,  g_oh);
    cudaGetSymbolAddress((void**)&x2,  g_x2);
    cudaGetSymbolAddress((void**)&h1h, g_h1h);
    cudaGetSymbolAddress((void**)&wt,  g_wt);
    cudaGetSymbolAddress((void**)&Tc,  g_Tc);
    cudaGetSymbolAddress((void**)&Pc,  g_Pc);
    cudaGetSymbolAddress((void**)&Sst, g_Sst);

    __half* wqkvgT = wt;                           // [6144][2048]
    __half* woT    = wqkvgT + (size_t)6144 * 2048;
    __half* w13T   = woT    + (size_t)2048 * 2048; // [11264][2048] interleaved
    __half* w2T    = w13T   + (size_t)11264 * 2048;

    cudaFuncSetAttribute(gemm_h<EPI_QKVG  >, cudaFuncAttributeMaxDynamicSharedMemorySize, GSMEM);
    cudaFuncSetAttribute(gemm_h<EPI_RES   >, cudaFuncAttributeMaxDynamicSharedMemorySize, GSMEM);
    cudaFuncSetAttribute(gemm_h<EPI_SWIGLU>, cudaFuncAttributeMaxDynamicSharedMemorySize, GSMEM);

    const size_t xElems  = (size_t)NTOK * D_MODEL;
    const size_t sfElems = (size_t)BDIM * NHEAD * 64 * 128;
    float* Sf = ((size_t)out_size >= xElems + sfElems) ? (out + xElems) : nullptr;

    const float kscale = 0.08838834764831843f;

    transpose_h<<<dim3(32,  64), 256>>>(Wq, wqkvgT,                     2048, 1024, 1.f,    1, 0);
    transpose_h<<<dim3(32,  64), 256>>>(Wk, wqkvgT + (size_t)1024*2048, 2048, 1024, kscale, 1, 0);
    transpose_h<<<dim3(64,  64), 256>>>(Wv, wqkvgT + (size_t)2048*2048, 2048, 2048, 1.f,    1, 0);
    transpose_h<<<dim3(64,  64), 256>>>(Wg, wqkvgT + (size_t)4096*2048, 2048, 2048, 1.f,    1, 0);
    transpose_h<<<dim3(64,  64), 256>>>(Wo, woT,  2048, 2048, 1.f, 1, 0);
    transpose_h<<<dim3(176, 64), 256>>>(W1, w13T, 2048, 5632, 1.f, 2, 0);
    transpose_h<<<dim3(176, 64), 256>>>(W3, w13T, 2048, 5632, 1.f, 2, 1);
    transpose_h<<<dim3(64, 176), 256>>>(W2, w2T,  5632, 2048, 1.f, 1, 0);

    rmsnorm_k<<<NTOK, 256>>>(x, ln1, xn);

    gemm_h<EPI_QKVG><<<dim3(48, 64), 128, GSMEM>>>(
        xn, wqkvgT, qk, NTOK, 6144, 2048, bg, vb, gb);

    kg1_k<<<NTOK / 8, 256>>>(xn, Wkg1, t16);
    kg2_k<<<(NTOK * 1024) / 256, 256>>>(t16, Wkg2, bkg2, egb);

    scan_p1<<<dim3(64, NCHUNK), 256>>>(qk, egb, vb, Tc, Pc);
    scan_p2<<<64, 256>>>(Tc, Pc, Sst);
    scan_p3<<<dim3(64, NCHUNK), 256>>>(qk, egb, vb, Sst, ob, Sf);

    gnorm_silu_k<<<(NTOK * NHEAD) / 8, 256>>>(ob, gb, oh);

    gemm_h<EPI_RES><<<dim3(16, 64), 128, GSMEM>>>(
        oh, woT, x2, NTOK, 2048, 2048, nullptr, x, nullptr);

    rmsnorm_k<<<NTOK, 256>>>(x2, ln2, xn);

    gemm_h<EPI_SWIGLU><<<dim3(88, 64), 128, GSMEM>>>(
        xn, w13T, h1h, NTOK, 11264, 2048, nullptr, nullptr, nullptr);

    gemm_h<EPI_RES><<<dim3(16, 64), 128, GSMEM>>>(
        h1h, w2T, out, NTOK, D_MODEL, HIDDEN, nullptr, x2, nullptr);
}

// round 10
// speedup vs baseline: 1.5887x; 1.0266x over previous
#include <cuda_runtime.h>
#include <cuda_fp16.h>
#include <cstdint>
#include <cstddef>

#define D_MODEL 2048
#define LSEQ    4096
#define BDIM    2
#define NTOK    (BDIM * LSEQ)      // 8192
#define NHEAD   16
#define HIDDEN  5632
#define NCHUNK  32
#define CLEN    (LSEQ / NCHUNK)    // 128

// ---------------- scratch (device globals; no allocation allowed) ----------------
__device__ __half g_xn [(size_t)NTOK * D_MODEL];
__device__ float  g_qk [(size_t)NTOK * 2048];             // q | k*scale
__device__ float  g_eg [(size_t)NTOK * 1024];
__device__ float  g_t16[(size_t)NTOK * 16];
__device__ float  g_v  [(size_t)NTOK * D_MODEL];
__device__ float  g_gt [(size_t)NTOK * D_MODEL];
__device__ __half g_oh [(size_t)NTOK * D_MODEL];
__device__ float  g_x2 [(size_t)NTOK * D_MODEL];
__device__ __half g_h1h[(size_t)NTOK * HIDDEN];
__device__ __half g_wt [51380224];
__device__ float  g_Tc [(size_t)NCHUNK * 64 * 64 * 64];   // per-chunk local state
__device__ float  g_Pc [(size_t)NCHUNK * 64 * 64];        // per-chunk gate product
__device__ float  g_Sst[(size_t)NCHUNK * 64 * 64 * 64];   // state entering chunk

__device__ __forceinline__ float siluf(float x) { return x / (1.f + __expf(-x)); }
__device__ __forceinline__ void cpa16(void* s, const void* g) {
    uint32_t a = (uint32_t)__cvta_generic_to_shared(s);
    asm volatile("cp.async.cg.shared.global [%0], [%1], 16;" :: "r"(a), "l"(g));
}

// ================= fp16 tensor-core GEMM =================
// C[M,N] = epi(A[M,K] @ Wt[N,K]^T). CTA 128x128, 128 threads, 4 warps (2m x 2n),
// warp tile 64x64. BK=64, 3 stages, 2 CTAs/SM, fragment double-buffering.
enum { EPI_QKVG = 0, EPI_RES = 3, EPI_SWIGLU = 5 };

#define BK    64
#define LDH   72                           // halves/row: 144B
#define AH    (128 * LDH)                  // 9216 halves
#define STGH  (2 * AH)
#define NST   3
#define GSMEM (NST * STGH * 2)             // 110592 B

#define LDSM4(r, a)                                                            \
    asm volatile("ldmatrix.sync.aligned.m8n8.x4.shared.b16 {%0,%1,%2,%3}, [%4];" \
        : "=r"((r)[0]), "=r"((r)[1]), "=r"((r)[2]), "=r"((r)[3]) : "r"(a))

__device__ __forceinline__ void mma_h(float* c, const uint32_t* a, const uint32_t* b) {
    asm volatile(
        "mma.sync.aligned.m16n8k16.row.col.f32.f16.f16.f32 "
        "{%0,%1,%2,%3}, {%4,%5,%6,%7}, {%8,%9}, {%0,%1,%2,%3};"
        : "+f"(c[0]), "+f"(c[1]), "+f"(c[2]), "+f"(c[3])
        : "r"(a[0]), "r"(a[1]), "r"(a[2]), "r"(a[3]), "r"(b[0]), "r"(b[1]));
}

template <int EPI>
__global__ __launch_bounds__(128, 2) void gemm_h(
    const __half* __restrict__ A, const __half* __restrict__ Wt, void* __restrict__ Cv,
    int M, int N, int K,
    const float* __restrict__ bias, const float* __restrict__ res,
    const float* __restrict__ aux)
{
    extern __shared__ __align__(16) __half hsm[];
    const int tid = threadIdx.x;
    const int wid = tid >> 5, lane = tid & 31;
    const int g = lane >> 2, tig = lane & 3;
    const int wm = (wid >> 1) * 64;
    const int wn = (wid & 1) * 64;
    const int m0 = blockIdx.y * 128;
    const int n0 = blockIdx.x * 128;
    const int nK = K >> 6;

    auto load_stage = [&](int slot, int kc) {
        __half* As = hsm + slot * STGH;
        __half* Bs = As + AH;
        const int k0 = kc * BK;
        const __half* Ag = A  + (size_t)m0 * K + k0;
        const __half* Bg = Wt + (size_t)n0 * K + k0;
        #pragma unroll
        for (int j = 0; j < 8; j++) {
            const int i = tid + j * 128;
            const int row = i >> 3, c = i & 7;
            cpa16(As + row * LDH + c * 8, Ag + (size_t)row * K + c * 8);
            cpa16(Bs + row * LDH + c * 8, Bg + (size_t)row * K + c * 8);
        }
        asm volatile("cp.async.commit_group;");
    };

    float acc[4][8][4];
    #pragma unroll
    for (int mt = 0; mt < 4; mt++)
        #pragma unroll
        for (int nt = 0; nt < 8; nt++)
            #pragma unroll
            for (int r = 0; r < 4; r++) acc[mt][nt][r] = 0.f;

    load_stage(0, 0);
    load_stage(1, 1);

    const uint32_t sbase = (uint32_t)__cvta_generic_to_shared(hsm);
    const int lrA = lane & 15;
    const int lkA = (lane >> 4) << 3;
    const int rB  = (lane & 7) + ((lane & 16) ? 8 : 0);
    const int lkB = (lane & 8) ? 8 : 0;

    for (int ks = 0; ks < nK; ks++) {
        const int slot = ks % 3;
        if (ks + 1 < nK) asm volatile("cp.async.wait_group 1;");
        else             asm volatile("cp.async.wait_group 0;");
        __syncthreads();
        if (ks + 2 < nK) load_stage((ks + 2) % 3, ks + 2);

        const uint32_t aB = sbase + (uint32_t)(slot * STGH) * 2;
        const uint32_t bB = aB + AH * 2;
        const uint32_t aAddr = aB + (uint32_t)((wm + lrA) * LDH + lkA) * 2;
        const uint32_t bAddr = bB + (uint32_t)((wn + rB) * LDH + lkB) * 2;

        uint32_t a[2][4][4], b[2][4][4];
        #pragma unroll
        for (int mt = 0; mt < 4; mt++)
            LDSM4(a[0][mt], aAddr + (uint32_t)(mt * 16 * LDH) * 2);
        #pragma unroll
        for (int np = 0; np < 4; np++)
            LDSM4(b[0][np], bAddr + (uint32_t)(np * 16 * LDH) * 2);

        #pragma unroll
        for (int kstep = 0; kstep < 4; kstep++) {
            const int cur = kstep & 1;
            if (kstep < 3) {                 // prefetch next kstep's fragments
                const int nxt = cur ^ 1;
                #pragma unroll
                for (int mt = 0; mt < 4; mt++)
                    LDSM4(a[nxt][mt], aAddr + (uint32_t)(mt * 16 * LDH) * 2 + (kstep + 1) * 32);
                #pragma unroll
                for (int np = 0; np < 4; np++)
                    LDSM4(b[nxt][np], bAddr + (uint32_t)(np * 16 * LDH) * 2 + (kstep + 1) * 32);
            }
            #pragma unroll
            for (int mt = 0; mt < 4; mt++)
                #pragma unroll
                for (int nt = 0; nt < 8; nt++)
                    mma_h(acc[mt][nt], a[cur][mt], &b[cur][nt >> 1][(nt & 1) * 2]);
        }
    }

    // ---- epilogue ----
    #pragma unroll
    for (int mt = 0; mt < 4; mt++) {
        #pragma unroll
        for (int hf = 0; hf < 2; hf++) {
            const size_t row = (size_t)m0 + wm + mt * 16 + g + hf * 8;
            #pragma unroll
            for (int nt = 0; nt < 8; nt++) {
                const int col = n0 + wn + nt * 8 + tig * 2;
                float v0 = acc[mt][nt][hf * 2 + 0];
                float v1 = acc[mt][nt][hf * 2 + 1];
                if (EPI == EPI_QKVG) {
                    float* dst;
                    int cl = col;
                    if (n0 < 2048)      { dst = (float*)Cv; }
                    else if (n0 < 4096) { dst = (float*)res; cl -= 2048; }
                    else {
                        dst = (float*)aux; cl -= 4096;
                        v0 += bias[cl]; v1 += bias[cl + 1];
                    }
                    *(float2*)(dst + row * 2048 + cl) = make_float2(v0, v1);
                } else if (EPI == EPI_RES) {
                    const size_t base = row * (size_t)N + col;
                    const float2 rv = *(const float2*)(res + base);
                    *(float2*)((float*)Cv + base) = make_float2(v0 + rv.x, v1 + rv.y);
                } else { // EPI_SWIGLU
                    ((__half*)Cv)[row * (size_t)(N >> 1) + (col >> 1)] =
                        __float2half_rn(siluf(v0) * v1);
                }
            }
        }
    }
}

// ------- 32x32 tiled transpose + fp16 convert; out row = c*rowMul + rowOff -------
__global__ __launch_bounds__(256) void transpose_h(const float* __restrict__ in,
                                                   __half* __restrict__ out,
                                                   int R, int Ccols, float scale,
                                                   int rowMul, int rowOff)
{
    __shared__ float tile[32][33];
    const int c0 = blockIdx.x * 32, r0 = blockIdx.y * 32;
    const int x = threadIdx.x & 31, y = threadIdx.x >> 5;
    #pragma unroll
    for (int i = 0; i < 32; i += 8)
        tile[y + i][x] = in[(size_t)(r0 + y + i) * Ccols + c0 + x] * scale;
    __syncthreads();
    #pragma unroll
    for (int i = 0; i < 32; i += 8)
        out[((size_t)(c0 + y + i) * rowMul + rowOff) * R + r0 + x] =
            __float2half_rn(tile[x][y + i]);
}

// ---------------- RMSNorm: fp32 in -> half out ----------------
__global__ __launch_bounds__(256) void rmsnorm_k(const float* __restrict__ x,
                                                 const float* __restrict__ w,
                                                 __half* __restrict__ y)
{
    const int row = blockIdx.x;
    const int tid = threadIdx.x;
    const float4* xr = (const float4*)(x + (size_t)row * D_MODEL);
    float4 v0 = xr[tid];
    float4 v1 = xr[tid + 256];
    float ss = v0.x*v0.x + v0.y*v0.y + v0.z*v0.z + v0.w*v0.w
             + v1.x*v1.x + v1.y*v1.y + v1.z*v1.z + v1.w*v1.w;
    #pragma unroll
    for (int off = 16; off; off >>= 1) ss += __shfl_xor_sync(0xffffffffu, ss, off);
    __shared__ float red[8];
    if ((tid & 31) == 0) red[tid >> 5] = ss;
    __syncthreads();
    if (tid < 32) {
        float t = (tid < 8) ? red[tid] : 0.f;
        #pragma unroll
        for (int off = 4; off; off >>= 1) t += __shfl_xor_sync(0xffffffffu, t, off);
        if (tid == 0) red[0] = t;
    }
    __syncthreads();
    const float scale = rsqrtf(red[0] * (1.f / (float)D_MODEL) + 1e-5f);
    const float4* wr = (const float4*)w;
    float4 w0 = wr[tid], w1 = wr[tid + 256];
    __half2* y2 = (__half2*)(y + (size_t)row * D_MODEL);
    y2[tid * 2]       = __floats2half2_rn(v0.x * scale * w0.x, v0.y * scale * w0.y);
    y2[tid * 2 + 1]   = __floats2half2_rn(v0.z * scale * w0.z, v0.w * scale * w0.w);
    y2[512 + tid * 2] = __floats2half2_rn(v1.x * scale * w1.x, v1.y * scale * w1.y);
    y2[513 + tid * 2] = __floats2half2_rn(v1.z * scale * w1.z, v1.w * scale * w1.w);
}

// ---------------- low-rank gate, stage 1 ----------------
__global__ __launch_bounds__(256) void kg1_k(const __half* __restrict__ xn,
                                             const float* __restrict__ W,
                                             float* __restrict__ t16)
{
    const int gw = (blockIdx.x * 256 + threadIdx.x) >> 5;
    const int lane = threadIdx.x & 31;
    if (gw >= NTOK) return;
    const __half2* xr = (const __half2*)(xn + (size_t)gw * D_MODEL);
    float acc[16];
    #pragma unroll
    for (int j = 0; j < 16; j++) acc[j] = 0.f;
    for (int k2 = lane; k2 < 1024; k2 += 32) {
        const float2 xv = __half22float2(xr[k2]);
        const float4* w0r = (const float4*)(W + (size_t)(2 * k2) * 16);
        const float4* w1r = (const float4*)(W + (size_t)(2 * k2 + 1) * 16);
        float4 A0 = w0r[0], A1 = w0r[1], A2 = w0r[2], A3 = w0r[3];
        float4 B0 = w1r[0], B1 = w1r[1], B2 = w1r[2], B3 = w1r[3];
        acc[0]  = fmaf(xv.x, A0.x, fmaf(xv.y, B0.x, acc[0]));
        acc[1]  = fmaf(xv.x, A0.y, fmaf(xv.y, B0.y, acc[1]));
        acc[2]  = fmaf(xv.x, A0.z, fmaf(xv.y, B0.z, acc[2]));
        acc[3]  = fmaf(xv.x, A0.w, fmaf(xv.y, B0.w, acc[3]));
        acc[4]  = fmaf(xv.x, A1.x, fmaf(xv.y, B1.x, acc[4]));
        acc[5]  = fmaf(xv.x, A1.y, fmaf(xv.y, B1.y, acc[5]));
        acc[6]  = fmaf(xv.x, A1.z, fmaf(xv.y, B1.z, acc[6]));
        acc[7]  = fmaf(xv.x, A1.w, fmaf(xv.y, B1.w, acc[7]));
        acc[8]  = fmaf(xv.x, A2.x, fmaf(xv.y, B2.x, acc[8]));
        acc[9]  = fmaf(xv.x, A2.y, fmaf(xv.y, B2.y, acc[9]));
        acc[10] = fmaf(xv.x, A2.z, fmaf(xv.y, B2.z, acc[10]));
        acc[11] = fmaf(xv.x, A2.w, fmaf(xv.y, B2.w, acc[11]));
        acc[12] = fmaf(xv.x, A3.x, fmaf(xv.y, B3.x, acc[12]));
        acc[13] = fmaf(xv.x, A3.y, fmaf(xv.y, B3.y, acc[13]));
        acc[14] = fmaf(xv.x, A3.z, fmaf(xv.y, B3.z, acc[14]));
        acc[15] = fmaf(xv.x, A3.w, fmaf(xv.y, B3.w, acc[15]));
    }
    #pragma unroll
    for (int j = 0; j < 16; j++) {
        #pragma unroll
        for (int off = 16; off; off >>= 1)
            acc[j] += __shfl_xor_sync(0xffffffffu, acc[j], off);
    }
    if (lane == 0) {
        float4* dst = (float4*)(t16 + (size_t)gw * 16);
        dst[0] = make_float4(acc[0],  acc[1],  acc[2],  acc[3]);
        dst[1] = make_float4(acc[4],  acc[5],  acc[6],  acc[7]);
        dst[2] = make_float4(acc[8],  acc[9],  acc[10], acc[11]);
        dst[3] = make_float4(acc[12], acc[13], acc[14], acc[15]);
    }
}

// ---- stage 2: eg = exp( log_sigmoid(t16 @ Wkg2 + b) / 16 ) ----
__global__ __launch_bounds__(256) void kg2_k(const float* __restrict__ t16,
                                             const float* __restrict__ W,
                                             const float* __restrict__ b,
                                             float* __restrict__ eg)
{
    const size_t idx = (size_t)blockIdx.x * 256 + threadIdx.x;
    const size_t t = idx >> 10;
    const int n = (int)(idx & 1023);
    const float* tr = t16 + t * 16;
    float z = b[n];
    #pragma unroll
    for (int j = 0; j < 16; j++) z = fmaf(tr[j], W[j * 1024 + n], z);
    const float ls = fminf(z, 0.f) - log1pf(__expf(-fabsf(z)));
    eg[idx] = __expf(ls * 0.0625f);
}

// ================ chunked GLA scan: 3 passes ================

// pass 1: per-chunk local state T and gate product P (half-head blocks, 256 thr)
__global__ __launch_bounds__(256) void scan_p1(const float* __restrict__ qk,
                                               const float* __restrict__ eg,
                                               const float* __restrict__ v,
                                               float* __restrict__ Tc,
                                               float* __restrict__ Pc)
{
    const int bhh = blockIdx.x;
    const int c   = blockIdx.y;
    const int bh = bhh >> 1, half = bhh & 1;
    const int b = bh >> 4, h = bh & 15;
    const int tid = threadIdx.x;
    const int dp = tid >> 2, g = tid & 3;

    __shared__ float sk[2][2][64], se[2][2][64], sv[2][2][64];
    float S[16], pe[16];
    #pragma unroll
    for (int j = 0; j < 16; j++) { S[j] = 0.f; pe[j] = 1.f; }

    const size_t tok0 = (size_t)b * LSEQ + (size_t)c * CLEN;
    const int i64 = tid & 63;
    const int sel = tid >> 6;

    auto loadslot = [&](int slot, int t0) {
        #pragma unroll
        for (int sub = 0; sub < 2; sub++) {
            const size_t base = tok0 + t0 + sub;
            if (sel == 1)      sk[slot][sub][i64] = qk[base * 2048 + 1024 + h * 64 + i64];
            else if (sel == 2) se[slot][sub][i64] = eg[base * 1024 + h * 64 + i64];
            else if (sel == 3) sv[slot][sub][i64] = v [base * 2048 + h * 128 + half * 64 + i64];
        }
    };

    loadslot(0, 0);
    __syncthreads();
    for (int t = 0; t < CLEN; t += 2) {
        const int p = (t >> 1) & 1;
        if (t + 2 < CLEN) loadslot(p ^ 1, t + 2);
        #pragma unroll
        for (int sub = 0; sub < 2; sub++) {
            const float vv = sv[p][sub][dp];
            #pragma unroll
            for (int j = 0; j < 16; j++) {
                const int kk = g * 16 + j;
                const float e = se[p][sub][kk];
                S[j]  = fmaf(S[j], e, sk[p][sub][kk] * vv);
                pe[j] *= e;
            }
        }
        __syncthreads();
    }

    const size_t tb = (((size_t)c * 64 + bhh) * 64 + dp) * 64 + g * 16;
    #pragma unroll
    for (int j = 0; j < 16; j++) Tc[tb + j] = S[j];
    if (dp == 0) {
        const size_t pb = ((size_t)c * 64 + bhh) * 64 + g * 16;
        #pragma unroll
        for (int j = 0; j < 16; j++) Pc[pb + j] = pe[j];
    }
}

// pass 2: sequential chunk combine
__global__ __launch_bounds__(256) void scan_p2(const float* __restrict__ Tc,
                                               const float* __restrict__ Pc,
                                               float* __restrict__ Sst)
{
    const int bhh = blockIdx.x;
    const int tid = threadIdx.x;
    const int dp = tid >> 2, g = tid & 3;
    float S[16];
    #pragma unroll
    for (int j = 0; j < 16; j++) S[j] = 0.f;
    for (int c = 0; c < NCHUNK; c++) {
        const size_t tb = (((size_t)c * 64 + bhh) * 64 + dp) * 64 + g * 16;
        const size_t pb = ((size_t)c * 64 + bhh) * 64 + g * 16;
        #pragma unroll
        for (int j = 0; j < 16; j++) Sst[tb + j] = S[j];
        #pragma unroll
        for (int j = 0; j < 16; j++) S[j] = fmaf(Pc[pb + j], S[j], Tc[tb + j]);
    }
}

// pass 3 (fused): replay chunk, buffer o in smem, groupnorm + silu(g) gate,
// write half oh directly (+ Sf on last chunk). Block = full head, 512 threads.
#define P3_SMEM ((128 * 128 + 3 * 256 + 512) * 4)   // 70656 B

__global__ __launch_bounds__(512) void scan_p3(const float* __restrict__ qk,
                                               const float* __restrict__ eg,
                                               const float* __restrict__ v,
                                               const float* __restrict__ Sst,
                                               const float* __restrict__ gt,
                                               __half* __restrict__ oh,
                                               float* __restrict__ Sf)
{
    extern __shared__ __align__(16) float p3s[];
    float* obuf = p3s;                 // [128 tokens][128 dims]
    float* sq   = obuf + 128 * 128;    // [2][2][64]
    float* sk   = sq + 256;
    float* se   = sk + 256;
    float* sv   = se + 256;            // [2][2][128]

    const int bh = blockIdx.x;         // 0..31
    const int c  = blockIdx.y;
    const int b = bh >> 4, h = bh & 15;
    const int tid = threadIdx.x;
    const int dp = tid >> 2;           // 0..127 (full head dim)
    const int g  = tid & 3;

    float S[16];
    {
        const int bhh = bh * 2 + (dp >> 6);
        const size_t tb = (((size_t)c * 64 + bhh) * 64 + (dp & 63)) * 64 + g * 16;
        #pragma unroll
        for (int j = 0; j < 16; j++) S[j] = Sst[tb + j];
    }

    const size_t tok0 = (size_t)b * LSEQ + (size_t)c * CLEN;
    const int grp = tid >> 7;          // 0..3: q, k, e, v
    const int gi  = tid & 127;

    auto loadslot = [&](int slot, int t0) {
        if (grp == 3) {                // v: 128 dims x 2 subs, 2 loads
            #pragma unroll
            for (int sub = 0; sub < 2; sub++)
                sv[(slot * 2 + sub) * 128 + gi] =
                    v[(tok0 + t0 + sub) * 2048 + h * 128 + gi];
        } else {
            const int sub = gi >> 6, i64 = gi & 63;
            const size_t base = tok0 + t0 + sub;
            if (grp == 0)      sq[(slot * 2 + sub) * 64 + i64] = qk[base * 2048 + h * 64 + i64];
            else if (grp == 1) sk[(slot * 2 + sub) * 64 + i64] = qk[base * 2048 + 1024 + h * 64 + i64];
            else               se[(slot * 2 + sub) * 64 + i64] = eg[base * 1024 + h * 64 + i64];
        }
    };

    loadslot(0, 0);
    __syncthreads();
    for (int t = 0; t < CLEN; t += 2) {
        const int p = (t >> 1) & 1;
        if (t + 2 < CLEN) loadslot(p ^ 1, t + 2);
        #pragma unroll
        for (int sub = 0; sub < 2; sub++) {
            const float vv = sv[(p * 2 + sub) * 128 + dp];
            float acc = 0.f;
            #pragma unroll
            for (int j = 0; j < 16; j++) {
                const int kk = g * 16 + j;
                S[j] = fmaf(S[j], se[(p * 2 + sub) * 64 + kk], sk[(p * 2 + sub) * 64 + kk] * vv);
                acc  = fmaf(sq[(p * 2 + sub) * 64 + kk], S[j], acc);
            }
            acc += __shfl_xor_sync(0xffffffffu, acc, 1);
            acc += __shfl_xor_sync(0xffffffffu, acc, 2);
            if (g == 0) obuf[(t + sub) * 128 + dp] = acc;
        }
        __syncthreads();
    }

    if (c == NCHUNK - 1 && Sf) {
        #pragma unroll
        for (int j = 0; j < 16; j++) {
            const int kk = g * 16 + j;
            Sf[(((size_t)b * 16 + h) * 64 + kk) * 128 + dp] = S[j];
        }
    }

    // ---- fused groupnorm + silu(g) gate: one warp per 8 tokens ----
    const int w = tid >> 5, lane = tid & 31;
    #pragma unroll
    for (int i = 0; i < 8; i++) {
        const int t = w * 8 + i;
        const float4 ov = *(const float4*)(obuf + t * 128 + lane * 4);
        float s  = ov.x + ov.y + ov.z + ov.w;
        float ss = ov.x*ov.x + ov.y*ov.y + ov.z*ov.z + ov.w*ov.w;
        #pragma unroll
        for (int off = 16; off; off >>= 1) {
            s  += __shfl_xor_sync(0xffffffffu, s,  off);
            ss += __shfl_xor_sync(0xffffffffu, ss, off);
        }
        const float mu = s * (1.f / 128.f);
        const float rs = rsqrtf(ss * (1.f / 128.f) - mu * mu + 1e-5f);
        const size_t base = (tok0 + t) * 2048 + (size_t)h * 128 + lane * 4;
        const float4 gv = *(const float4*)(gt + base);
        __half2* op = (__half2*)(oh + base);
        op[0] = __floats2half2_rn(siluf(gv.x) * ((ov.x - mu) * rs),
                                  siluf(gv.y) * ((ov.y - mu) * rs));
        op[1] = __floats2half2_rn(siluf(gv.z) * ((ov.z - mu) * rs),
                                  siluf(gv.w) * ((ov.w - mu) * rs));
    }
}

// ---------------- launch ----------------
extern "C" void kernel_launch(void* const* d_in, const int* in_sizes, int n_in,
                              void* d_out, int out_size)
{
    (void)in_sizes; (void)n_in;
    const float* x    = (const float*)d_in[0];
    const float* Wq   = (const float*)d_in[1];
    const float* Wk   = (const float*)d_in[2];
    const float* Wkg1 = (const float*)d_in[3];
    const float* Wkg2 = (const float*)d_in[4];
    const float* bkg2 = (const float*)d_in[5];
    const float* Wv   = (const float*)d_in[6];
    const float* Wg   = (const float*)d_in[7];
    const float* bg   = (const float*)d_in[8];
    const float* Wo   = (const float*)d_in[9];
    const float* ln1  = (const float*)d_in[10];
    const float* ln2  = (const float*)d_in[11];
    const float* W1   = (const float*)d_in[12];
    const float* W3   = (const float*)d_in[13];
    const float* W2   = (const float*)d_in[14];
    float* out = (float*)d_out;

    __half *xn, *oh, *h1h, *wt;
    float *qk, *egb, *t16, *vb, *gb, *x2, *Tc, *Pc, *Sst;
    cudaGetSymbolAddress((void**)&xn,  g_xn);
    cudaGetSymbolAddress((void**)&qk,  g_qk);
    cudaGetSymbolAddress((void**)&egb, g_eg);
    cudaGetSymbolAddress((void**)&t16, g_t16);
    cudaGetSymbolAddress((void**)&vb,  g_v);
    cudaGetSymbolAddress((void**)&gb,  g_gt);
    cudaGetSymbolAddress((void**)&oh,  g_oh);
    cudaGetSymbolAddress((void**)&x2,  g_x2);
    cudaGetSymbolAddress((void**)&h1h, g_h1h);
    cudaGetSymbolAddress((void**)&wt,  g_wt);
    cudaGetSymbolAddress((void**)&Tc,  g_Tc);
    cudaGetSymbolAddress((void**)&Pc,  g_Pc);
    cudaGetSymbolAddress((void**)&Sst, g_Sst);

    __half* wqkvgT = wt;                           // [6144][2048]
    __half* woT    = wqkvgT + (size_t)6144 * 2048;
    __half* w13T   = woT    + (size_t)2048 * 2048; // [11264][2048] interleaved
    __half* w2T    = w13T   + (size_t)11264 * 2048;

    cudaFuncSetAttribute(gemm_h<EPI_QKVG  >, cudaFuncAttributeMaxDynamicSharedMemorySize, GSMEM);
    cudaFuncSetAttribute(gemm_h<EPI_RES   >, cudaFuncAttributeMaxDynamicSharedMemorySize, GSMEM);
    cudaFuncSetAttribute(gemm_h<EPI_SWIGLU>, cudaFuncAttributeMaxDynamicSharedMemorySize, GSMEM);
    cudaFuncSetAttribute(scan_p3, cudaFuncAttributeMaxDynamicSharedMemorySize, P3_SMEM);

    const size_t xElems  = (size_t)NTOK * D_MODEL;
    const size_t sfElems = (size_t)BDIM * NHEAD * 64 * 128;
    float* Sf = ((size_t)out_size >= xElems + sfElems) ? (out + xElems) : nullptr;

    const float kscale = 0.08838834764831843f;

    // launches 1-4: qkvg weight transposes; 5: rmsnorm; 6: QKVG GEMM (ncu -s 5 target)
    transpose_h<<<dim3(32,  64), 256>>>(Wq, wqkvgT,                     2048, 1024, 1.f,    1, 0);
    transpose_h<<<dim3(32,  64), 256>>>(Wk, wqkvgT + (size_t)1024*2048, 2048, 1024, kscale, 1, 0);
    transpose_h<<<dim3(64,  64), 256>>>(Wv, wqkvgT + (size_t)2048*2048, 2048, 2048, 1.f,    1, 0);
    transpose_h<<<dim3(64,  64), 256>>>(Wg, wqkvgT + (size_t)4096*2048, 2048, 2048, 1.f,    1, 0);

    rmsnorm_k<<<NTOK, 256>>>(x, ln1, xn);

    gemm_h<EPI_QKVG><<<dim3(48, 64), 128, GSMEM>>>(
        xn, wqkvgT, qk, NTOK, 6144, 2048, bg, vb, gb);

    // remaining transposes (independent of the attention path until their GEMMs)
    transpose_h<<<dim3(64,  64), 256>>>(Wo, woT,  2048, 2048, 1.f, 1, 0);
    transpose_h<<<dim3(176, 64), 256>>>(W1, w13T, 2048, 5632, 1.f, 2, 0);
    transpose_h<<<dim3(176, 64), 256>>>(W3, w13T, 2048, 5632, 1.f, 2, 1);
    transpose_h<<<dim3(64, 176), 256>>>(W2, w2T,  5632, 2048, 1.f, 1, 0);

    kg1_k<<<NTOK / 8, 256>>>(xn, Wkg1, t16);
    kg2_k<<<(NTOK * 1024) / 256, 256>>>(t16, Wkg2, bkg2, egb);

    scan_p1<<<dim3(64, NCHUNK), 256>>>(qk, egb, vb, Tc, Pc);
    scan_p2<<<64, 256>>>(Tc, Pc, Sst);
    scan_p3<<<dim3(32, NCHUNK), 512, P3_SMEM>>>(qk, egb, vb, Sst, gb, oh, Sf);

    gemm_h<EPI_RES><<<dim3(16, 64), 128, GSMEM>>>(
        oh, woT, x2, NTOK, 2048, 2048, nullptr, x, nullptr);

    rmsnorm_k<<<NTOK, 256>>>(x2, ln2, xn);

    gemm_h<EPI_SWIGLU><<<dim3(88, 64), 128, GSMEM>>>(
        xn, w13T, h1h, NTOK, 11264, 2048, nullptr, nullptr, nullptr);

    gemm_h<EPI_RES><<<dim3(16, 64), 128, GSMEM>>>(
        h1h, w2T, out, NTOK, D_MODEL, HIDDEN, nullptr, x2, nullptr);
}